// round 16
// baseline (speedup 1.0000x reference)
#include <cuda_runtime.h>
#include <cuda_fp16.h>
#include <math.h>
#include <stdint.h>

// GPT-2 small forward: B=2, T=1024, L=12, C=1024, H=16, D=64, V=50257
#define Bc 2
#define Tc 1024
#define Cc 1024
#define Hc 16
#define Dc 64
#define Lc 12
#define Vc 50257
#define Vpad 50432        // 197*256
#define Mc (Bc*Tc)        // 2048 tokens

// -------------------- scratch (device globals; no allocation) --------------------
__device__ float  g_x[Mc*Cc];          // residual stream (fp32)
__device__ __half g_h_h[Mc*Cc];        // layernorm output (fp16)
__device__ __half g_att_h[Mc*Cc];      // attention output (fp16)
__device__ __half g_fc_h[Mc*4*Cc];     // mlp hidden (fp16, post-gelu)
__device__ __half g_qkv_h[Mc*3*Cc];    // qkv (fp16)
__device__ __half g_wqkv_h[Lc*Cc*3*Cc];
__device__ __half g_wproj_h[Lc*Cc*Cc];
__device__ __half g_wfc_h[Lc*Cc*4*Cc];
__device__ __half g_wfcp_h[Lc*4*Cc*Cc];
__device__ __half g_wlm_h[Cc*Vpad];

// -------------------- helpers --------------------
__device__ __forceinline__ float gelu_f(float x) {
    const float k = 0.7978845608028654f;
    float x3 = x*x*x;
    return 0.5f*x*(1.0f + tanhf(k*(x + 0.044715f*x3)));
}
__device__ __forceinline__ uint32_t smem_u32(const void* p) {
    uint32_t a;
    asm("{ .reg .u64 t; cvta.to.shared.u64 t, %1; cvt.u32.u64 %0, t; }" : "=r"(a) : "l"(p));
    return a;
}
__device__ __forceinline__ unsigned pack_h2(float lo, float hi) {
    __half2 h = __floats2half2_rn(lo, hi);
    return *reinterpret_cast<unsigned*>(&h);
}

template<int NT>
__device__ __forceinline__ float blockSum(float v, float* red) {
    #pragma unroll
    for (int o = 16; o > 0; o >>= 1) v += __shfl_xor_sync(0xffffffffu, v, o);
    int w = threadIdx.x >> 5;
    if ((threadIdx.x & 31) == 0) red[w] = v;
    __syncthreads();
    if (threadIdx.x == 0) {
        float s = 0.f;
        #pragma unroll
        for (int i = 0; i < NT/32; i++) s += red[i];
        red[0] = s;
    }
    __syncthreads();
    float r = red[0];
    __syncthreads();
    return r;
}

// -------------------- weight conversion --------------------
__global__ void cvt_flat8(const float4* __restrict__ src, uint4* __restrict__ dst, int n8) {
    int i = blockIdx.x*256 + threadIdx.x;
    if (i >= n8) return;
    float4 a = src[2*i], b = src[2*i+1];
    uint4 o;
    o.x = pack_h2(a.x, a.y); o.y = pack_h2(a.z, a.w);
    o.z = pack_h2(b.x, b.y); o.w = pack_h2(b.z, b.w);
    dst[i] = o;
}
__global__ void cvt_pad4(const float* __restrict__ src, uint2* __restrict__ dst, int n4) {
    int i = blockIdx.x*256 + threadIdx.x;
    if (i >= n4) return;
    int base = i*4;
    int row = base / Vpad, n = base - row*Vpad;
    float v[4];
    #pragma unroll
    for (int j = 0; j < 4; j++) {
        int c = n + j;
        v[j] = (c < Vc) ? __ldg(src + (size_t)row*Vc + c) : 0.f;
    }
    uint2 o; o.x = pack_h2(v[0], v[1]); o.y = pack_h2(v[2], v[3]);
    dst[i] = o;
}

// -------------------- embedding --------------------
__global__ void embed_kernel(const int* __restrict__ idx,
                             const float* __restrict__ wte,
                             const float* __restrict__ wpe) {
    int i = blockIdx.x*blockDim.x + threadIdx.x;
    if (i >= Mc*Cc) return;
    int row = i / Cc, c = i - row*Cc;
    int t = row & (Tc-1);
    g_x[i] = wte[(size_t)idx[row]*Cc + c] + wpe[t*Cc + c];
}

// -------------------- layernorm: fp32 in -> fp16 out --------------------
__global__ void ln_kernel(const float* __restrict__ in, __half* __restrict__ out,
                          const float* __restrict__ w, const float* __restrict__ b) {
    __shared__ float red[8];
    int row = blockIdx.x;
    const float* xr = in + (size_t)row*Cc;
    float v[4];
    float s = 0.f;
    #pragma unroll
    for (int i = 0; i < 4; i++) { v[i] = xr[threadIdx.x + i*256]; s += v[i]; }
    s = blockSum<256>(s, red);
    float mean = s * (1.0f/Cc);
    float vs = 0.f;
    #pragma unroll
    for (int i = 0; i < 4; i++) { float d = v[i]-mean; vs += d*d; }
    vs = blockSum<256>(vs, red);
    float rstd = rsqrtf(vs*(1.0f/Cc) + 1e-5f);
    __half* orow = out + (size_t)row*Cc;
    #pragma unroll
    for (int i = 0; i < 4; i++) {
        int c = threadIdx.x + i*256;
        orow[c] = __float2half((v[i]-mean)*rstd*w[c] + b[c]);
    }
}

// ==================== fp16 GEMM: 3-stage cp.async, templated tile ====================
// C[M,N] = A[M,K](half) @ B[K,N](half) (+bias)(gelu)(+resid)
// 128 x BN tile, BK=32, 256 threads (8 warps 2x4), m16n8k16.
#define ASH 40

__device__ __forceinline__ void mma_f16(float& c0, float& c1, float& c2, float& c3,
                                        unsigned a0, unsigned a1, unsigned a2, unsigned a3,
                                        unsigned b0, unsigned b1) {
    asm volatile(
        "mma.sync.aligned.m16n8k16.row.col.f32.f16.f16.f32 "
        "{%0,%1,%2,%3},{%4,%5,%6,%7},{%8,%9},{%0,%1,%2,%3};"
        : "+f"(c0), "+f"(c1), "+f"(c2), "+f"(c3)
        : "r"(a0), "r"(a1), "r"(a2), "r"(a3), "r"(b0), "r"(b1));
}
__device__ __forceinline__ void ldsm_x4(unsigned& r0, unsigned& r1, unsigned& r2, unsigned& r3,
                                        uint32_t addr) {
    asm volatile("ldmatrix.sync.aligned.m8n8.x4.shared.b16 {%0,%1,%2,%3}, [%4];"
                 : "=r"(r0), "=r"(r1), "=r"(r2), "=r"(r3) : "r"(addr));
}
__device__ __forceinline__ void ldsm_x2(unsigned& r0, unsigned& r1, uint32_t addr) {
    asm volatile("ldmatrix.sync.aligned.m8n8.x2.shared.b16 {%0,%1}, [%2];"
                 : "=r"(r0), "=r"(r1) : "r"(addr));
}
__device__ __forceinline__ void ldsm_x2t(unsigned& r0, unsigned& r1, uint32_t addr) {
    asm volatile("ldmatrix.sync.aligned.m8n8.x2.trans.shared.b16 {%0,%1}, [%2];"
                 : "=r"(r0), "=r"(r1) : "r"(addr));
}
__device__ __forceinline__ void cpa16(uint32_t dst, const void* src) {
    asm volatile("cp.async.cg.shared.global [%0], [%1], 16;" :: "r"(dst), "l"(src) : "memory");
}

template<int BN>
__global__ void __launch_bounds__(256, (BN == 128) ? 2 : 1)
gemm_hh(const __half* __restrict__ A, int lda,
        const __half* __restrict__ Bh, int ldb,
        const float* __restrict__ bias, const float* __restrict__ resid,
        float* __restrict__ Cm, __half* __restrict__ Ch,
        int M, int N, int K, int do_gelu) {
    constexpr int BSH = BN + 8;
    constexpr int NT  = BN / 32;        // n-tiles per warp (warp covers BN/4)
    constexpr int ASZ = 128 * ASH;      // halves per A stage
    constexpr int BSZ = 32 * BSH;       // halves per B stage
    extern __shared__ __half dsm[];

    const int tid = threadIdx.x;
    const int lane = tid & 31, wid = tid >> 5;
    const int wm = wid >> 2, wn = wid & 3;
    const int bm = blockIdx.y*128, bn = blockIdx.x*BN;

    auto As = [&](int s) -> __half* { return dsm + s*ASZ; };
    auto Bs = [&](int s) -> __half* { return dsm + 3*ASZ + s*BSZ; };

    auto loadTiles = [&](int k0, int s) {
        __half* as = As(s);
        #pragma unroll
        for (int i = 0; i < 2; i++) {              // A: 128 rows x 4 16B-chunks
            int e = tid + i*256;
            int row = e >> 2, c = (e & 3) << 3;
            cpa16(smem_u32(&as[row*ASH + c]), A + (size_t)(bm+row)*lda + k0 + c);
        }
        __half* bs = Bs(s);
        #pragma unroll
        for (int i = 0; i < BN/64; i++) {          // B: 32 rows x BN/8 16B-chunks
            int e = tid + i*256;
            int row = e / (BN/8), c = (e % (BN/8)) << 3;
            cpa16(smem_u32(&bs[row*BSH + c]), Bh + (size_t)(k0+row)*ldb + bn + c);
        }
    };

    float acc[4][NT][4];
    #pragma unroll
    for (int i = 0; i < 4; i++)
        #pragma unroll
        for (int j = 0; j < NT; j++)
            #pragma unroll
            for (int r = 0; r < 4; r++) acc[i][j][r] = 0.f;

    const int NC = K >> 5;
    loadTiles(0, 0);
    asm volatile("cp.async.commit_group;" ::: "memory");
    loadTiles(32, 1);
    asm volatile("cp.async.commit_group;" ::: "memory");
    asm volatile("cp.async.wait_group 1;" ::: "memory");
    __syncthreads();

    const int a_lm_row = wm*64 + (lane & 15);
    const int a_lm_k   = (lane >> 4) << 3;
    const int b_lm_k   = lane & 15;
    const int b_lm_n   = wn*(BN/4);

    for (int c = 0; c < NC; c++) {
        if (c + 2 < NC) loadTiles((c+2) << 5, (c+2) % 3);
        asm volatile("cp.async.commit_group;" ::: "memory");

        const __half* as = As(c % 3);
        const __half* bs = Bs(c % 3);
        #pragma unroll
        for (int ks = 0; ks < 2; ks++) {
            unsigned a[4][4], b[NT][2];
            #pragma unroll
            for (int mt = 0; mt < 4; mt++) {
                uint32_t addr = smem_u32(&as[(a_lm_row + mt*16)*ASH + ks*16 + a_lm_k]);
                ldsm_x4(a[mt][0], a[mt][1], a[mt][2], a[mt][3], addr);
            }
            #pragma unroll
            for (int nt = 0; nt < NT; nt++) {
                uint32_t addr = smem_u32(&bs[(ks*16 + b_lm_k)*BSH + b_lm_n + nt*8]);
                ldsm_x2t(b[nt][0], b[nt][1], addr);
            }
            #pragma unroll
            for (int mt = 0; mt < 4; mt++)
                #pragma unroll
                for (int nt = 0; nt < NT; nt++)
                    mma_f16(acc[mt][nt][0], acc[mt][nt][1], acc[mt][nt][2], acc[mt][nt][3],
                            a[mt][0], a[mt][1], a[mt][2], a[mt][3],
                            b[nt][0], b[nt][1]);
        }
        asm volatile("cp.async.wait_group 1;" ::: "memory");
        __syncthreads();
    }

    const int r0 = bm + wm*64 + (lane >> 2);
    const int c0 = bn + wn*(BN/4) + ((lane & 3) << 1);
    #pragma unroll
    for (int mt = 0; mt < 4; mt++) {
        #pragma unroll
        for (int nt = 0; nt < NT; nt++) {
            int cc = c0 + nt*8;
            #pragma unroll
            for (int half = 0; half < 2; half++) {
                int r = r0 + mt*16 + half*8;
                #pragma unroll
                for (int j = 0; j < 2; j++) {
                    int c = cc + j;
                    if (c < N) {
                        float v = acc[mt][nt][half*2 + j];
                        if (bias) v += bias[c];
                        if (do_gelu) v = gelu_f(v);
                        size_t o = (size_t)r*N + c;
                        if (resid) v += resid[o];
                        if (Cm) Cm[o] = v;
                        if (Ch) Ch[o] = __float2half(v);
                    }
                }
            }
        }
    }
}

// smem sizes (bytes) for the two instantiations
#define SMEM_G128 (3*(128*ASH + 32*(128+8))*2)
#define SMEM_G256 (3*(128*ASH + 32*(256+8))*2)

// ==================== fp16 tensor-core flash attention ====================
#define ATS 72

__global__ void __launch_bounds__(128)
attn_mma_kernel(const __half* __restrict__ qkvh, __half* __restrict__ outh) {
    __shared__ __half Qs[64*ATS];
    __shared__ __half Ks[64*ATS];
    __shared__ __half Vs[64*ATS];

    const int q0 = blockIdx.x * 64;
    const int h  = blockIdx.y;
    const int b  = blockIdx.z;
    const int tid = threadIdx.x;
    const int lane = tid & 31, w = tid >> 5;
    const int qw = q0 + w*16;
    const int td = qw >> 6;

    #pragma unroll
    for (int i = 0; i < 4; i++) {
        int idx = tid + i*128;
        int q = idx >> 3, d8 = (idx & 7) << 3;
        *reinterpret_cast<uint4*>(&Qs[q*ATS + d8]) =
            *reinterpret_cast<const uint4*>(qkvh + (size_t)(b*Tc + q0 + q)*3*Cc + h*Dc + d8);
    }

    float o[8][4];
    #pragma unroll
    for (int i = 0; i < 8; i++)
        #pragma unroll
        for (int j = 0; j < 4; j++) o[i][j] = 0.f;
    float m0 = -1e30f, m1 = -1e30f, l0 = 0.f, l1 = 0.f;
    unsigned qa[4][4];
    bool qloaded = false;

    const int ntiles = (q0 >> 6) + 1;
    for (int t = 0; t < ntiles; t++) {
        __syncthreads();
        #pragma unroll
        for (int i = 0; i < 4; i++) {
            int idx = tid + i*128;
            int s = idx >> 3, d8 = (idx & 7) << 3;
            const __half* base = qkvh + (size_t)(b*Tc + t*64 + s)*3*Cc + h*Dc + d8;
            *reinterpret_cast<uint4*>(&Ks[s*ATS + d8]) =
                *reinterpret_cast<const uint4*>(base + Cc);
            *reinterpret_cast<uint4*>(&Vs[s*ATS + d8]) =
                *reinterpret_cast<const uint4*>(base + 2*Cc);
        }
        __syncthreads();

        if (!qloaded) {
            #pragma unroll
            for (int kc = 0; kc < 4; kc++) {
                uint32_t addr = smem_u32(&Qs[(w*16 + (lane & 15))*ATS + kc*16 + ((lane >> 4) << 3)]);
                ldsm_x4(qa[kc][0], qa[kc][1], qa[kc][2], qa[kc][3], addr);
            }
            qloaded = true;
        }
        if (t > td) continue;

        float sc[8][4];
        #pragma unroll
        for (int i = 0; i < 8; i++)
            #pragma unroll
            for (int j = 0; j < 4; j++) sc[i][j] = 0.f;
        #pragma unroll
        for (int kc = 0; kc < 4; kc++) {
            #pragma unroll
            for (int nt = 0; nt < 8; nt++) {
                unsigned b0, b1;
                uint32_t addr = smem_u32(&Ks[(nt*8 + (lane & 7))*ATS + kc*16 + (((lane >> 3) & 1) << 3)]);
                ldsm_x2(b0, b1, addr);
                mma_f16(sc[nt][0], sc[nt][1], sc[nt][2], sc[nt][3],
                        qa[kc][0], qa[kc][1], qa[kc][2], qa[kc][3], b0, b1);
            }
        }

        const int qr0 = qw + (lane >> 2), qr1 = qr0 + 8;
        #pragma unroll
        for (int nt = 0; nt < 8; nt++) {
            int sb = t*64 + nt*8 + ((lane & 3) << 1);
            #pragma unroll
            for (int j = 0; j < 4; j++) sc[nt][j] *= 0.125f;
            if (t == td) {
                if (sb     > qr0) sc[nt][0] = -1e30f;
                if (sb + 1 > qr0) sc[nt][1] = -1e30f;
                if (sb     > qr1) sc[nt][2] = -1e30f;
                if (sb + 1 > qr1) sc[nt][3] = -1e30f;
            }
        }

        float mx0 = -1e30f, mx1 = -1e30f;
        #pragma unroll
        for (int nt = 0; nt < 8; nt++) {
            mx0 = fmaxf(mx0, fmaxf(sc[nt][0], sc[nt][1]));
            mx1 = fmaxf(mx1, fmaxf(sc[nt][2], sc[nt][3]));
        }
        mx0 = fmaxf(mx0, __shfl_xor_sync(0xffffffffu, mx0, 1));
        mx0 = fmaxf(mx0, __shfl_xor_sync(0xffffffffu, mx0, 2));
        mx1 = fmaxf(mx1, __shfl_xor_sync(0xffffffffu, mx1, 1));
        mx1 = fmaxf(mx1, __shfl_xor_sync(0xffffffffu, mx1, 2));
        float mn0 = fmaxf(m0, mx0), mn1 = fmaxf(m1, mx1);
        float al0 = __expf(m0 - mn0), al1 = __expf(m1 - mn1);
        float ls0 = 0.f, ls1 = 0.f;
        #pragma unroll
        for (int nt = 0; nt < 8; nt++) {
            sc[nt][0] = __expf(sc[nt][0] - mn0);
            sc[nt][1] = __expf(sc[nt][1] - mn0);
            sc[nt][2] = __expf(sc[nt][2] - mn1);
            sc[nt][3] = __expf(sc[nt][3] - mn1);
            ls0 += sc[nt][0] + sc[nt][1];
            ls1 += sc[nt][2] + sc[nt][3];
        }
        ls0 += __shfl_xor_sync(0xffffffffu, ls0, 1);
        ls0 += __shfl_xor_sync(0xffffffffu, ls0, 2);
        ls1 += __shfl_xor_sync(0xffffffffu, ls1, 1);
        ls1 += __shfl_xor_sync(0xffffffffu, ls1, 2);
        l0 = l0*al0 + ls0;  m0 = mn0;
        l1 = l1*al1 + ls1;  m1 = mn1;
        #pragma unroll
        for (int nt = 0; nt < 8; nt++) {
            o[nt][0] *= al0; o[nt][1] *= al0;
            o[nt][2] *= al1; o[nt][3] *= al1;
        }

        unsigned pa[4][4];
        #pragma unroll
        for (int kc = 0; kc < 4; kc++) {
            pa[kc][0] = pack_h2(sc[2*kc  ][0], sc[2*kc  ][1]);
            pa[kc][1] = pack_h2(sc[2*kc  ][2], sc[2*kc  ][3]);
            pa[kc][2] = pack_h2(sc[2*kc+1][0], sc[2*kc+1][1]);
            pa[kc][3] = pack_h2(sc[2*kc+1][2], sc[2*kc+1][3]);
        }

        #pragma unroll
        for (int kc = 0; kc < 4; kc++) {
            #pragma unroll
            for (int nt = 0; nt < 8; nt++) {
                unsigned b0, b1;
                uint32_t addr = smem_u32(&Vs[(kc*16 + (lane & 15))*ATS + nt*8]);
                ldsm_x2t(b0, b1, addr);
                mma_f16(o[nt][0], o[nt][1], o[nt][2], o[nt][3],
                        pa[kc][0], pa[kc][1], pa[kc][2], pa[kc][3], b0, b1);
            }
        }
    }

    float inv0 = 1.0f / l0, inv1 = 1.0f / l1;
    const int qr0 = qw + (lane >> 2), qr1 = qr0 + 8;
    #pragma unroll
    for (int nt = 0; nt < 8; nt++) {
        int d = nt*8 + ((lane & 3) << 1);
        __half* p0 = outh + (size_t)(b*Tc + qr0)*Cc + h*Dc + d;
        __half* p1 = outh + (size_t)(b*Tc + qr1)*Cc + h*Dc + d;
        *reinterpret_cast<__half2*>(p0) = __floats2half2_rn(o[nt][0]*inv0, o[nt][1]*inv0);
        *reinterpret_cast<__half2*>(p1) = __floats2half2_rn(o[nt][2]*inv1, o[nt][3]*inv1);
    }
}

// -------------------- launch --------------------
extern "C" void kernel_launch(void* const* d_in, const int* in_sizes, int n_in,
                              void* d_out, int out_size) {
    const int*   idx       = (const int*)  d_in[0];
    const float* wte       = (const float*)d_in[1];
    const float* wpe       = (const float*)d_in[2];
    const float* ln1_w     = (const float*)d_in[3];
    const float* ln1_b     = (const float*)d_in[4];
    const float* attn_w    = (const float*)d_in[5];
    const float* attn_b    = (const float*)d_in[6];
    const float* proj_w    = (const float*)d_in[7];
    const float* proj_b    = (const float*)d_in[8];
    const float* ln2_w     = (const float*)d_in[9];
    const float* ln2_b     = (const float*)d_in[10];
    const float* fc_w      = (const float*)d_in[11];
    const float* fc_b      = (const float*)d_in[12];
    const float* fcproj_w  = (const float*)d_in[13];
    const float* fcproj_b  = (const float*)d_in[14];
    const float* lnf_w     = (const float*)d_in[15];
    const float* lnf_b     = (const float*)d_in[16];
    const float* lm_head_w = (const float*)d_in[17];
    float* out = (float*)d_out;

    float *x;
    __half *hh, *atth, *fch, *qkvh, *wqkv, *wproj, *wfc, *wfcp, *wlm;
    cudaGetSymbolAddress((void**)&x,    g_x);
    cudaGetSymbolAddress((void**)&hh,   g_h_h);
    cudaGetSymbolAddress((void**)&atth, g_att_h);
    cudaGetSymbolAddress((void**)&fch,  g_fc_h);
    cudaGetSymbolAddress((void**)&qkvh, g_qkv_h);
    cudaGetSymbolAddress((void**)&wqkv, g_wqkv_h);
    cudaGetSymbolAddress((void**)&wproj,g_wproj_h);
    cudaGetSymbolAddress((void**)&wfc,  g_wfc_h);
    cudaGetSymbolAddress((void**)&wfcp, g_wfcp_h);
    cudaGetSymbolAddress((void**)&wlm,  g_wlm_h);

    cudaFuncSetAttribute(gemm_hh<128>, cudaFuncAttributeMaxDynamicSharedMemorySize, SMEM_G128);
    cudaFuncSetAttribute(gemm_hh<256>, cudaFuncAttributeMaxDynamicSharedMemorySize, SMEM_G256);

    // ---- convert weights to fp16 ----
    {
        int n1 = Lc*Cc*3*Cc/8;
        cvt_flat8<<<(n1+255)/256, 256>>>((const float4*)attn_w, (uint4*)wqkv, n1);
        int n2 = Lc*Cc*Cc/8;
        cvt_flat8<<<(n2+255)/256, 256>>>((const float4*)proj_w, (uint4*)wproj, n2);
        int n3 = Lc*Cc*4*Cc/8;
        cvt_flat8<<<(n3+255)/256, 256>>>((const float4*)fc_w, (uint4*)wfc, n3);
        int n4 = Lc*4*Cc*Cc/8;
        cvt_flat8<<<(n4+255)/256, 256>>>((const float4*)fcproj_w, (uint4*)wfcp, n4);
        int n5 = Cc*Vpad/4;
        cvt_pad4<<<(n5+255)/256, 256>>>(lm_head_w, (uint2*)wlm, n5);
    }

    embed_kernel<<<(Mc*Cc + 255)/256, 256>>>(idx, wte, wpe);

    dim3 gQKV(3*Cc/256, Mc/128);
    dim3 gPROJ(Cc/128, Mc/128);
    dim3 gFC(4*Cc/256, Mc/128);
    dim3 gHEAD(Vpad/256, Mc/128);
    dim3 gATT(Tc/64, Hc, Bc);

    for (int l = 0; l < Lc; l++) {
        ln_kernel<<<Mc, 256>>>(x, hh, ln1_w + l*Cc, ln1_b + l*Cc);
        gemm_hh<256><<<gQKV, 256, SMEM_G256>>>(hh, Cc, wqkv + (size_t)l*Cc*3*Cc, 3*Cc,
                                               attn_b + (size_t)l*3*Cc, nullptr,
                                               nullptr, qkvh, Mc, 3*Cc, Cc, 0);
        attn_mma_kernel<<<gATT, 128>>>(qkvh, atth);
        gemm_hh<128><<<gPROJ, 256, SMEM_G128>>>(atth, Cc, wproj + (size_t)l*Cc*Cc, Cc,
                                                proj_b + (size_t)l*Cc, x,
                                                x, nullptr, Mc, Cc, Cc, 0);
        ln_kernel<<<Mc, 256>>>(x, hh, ln2_w + l*Cc, ln2_b + l*Cc);
        gemm_hh<256><<<gFC, 256, SMEM_G256>>>(hh, Cc, wfc + (size_t)l*Cc*4*Cc, 4*Cc,
                                              fc_b + (size_t)l*4*Cc, nullptr,
                                              nullptr, fch, Mc, 4*Cc, Cc, 1);
        gemm_hh<128><<<gPROJ, 256, SMEM_G128>>>(fch, 4*Cc, wfcp + (size_t)l*4*Cc*Cc, Cc,
                                                fcproj_b + (size_t)l*Cc, x,
                                                x, nullptr, Mc, Cc, 4*Cc, 0);
    }

    ln_kernel<<<Mc, 256>>>(x, hh, lnf_w, lnf_b);
    gemm_hh<256><<<gHEAD, 256, SMEM_G256>>>(hh, Cc, wlm, Vpad, nullptr, nullptr,
                                            out, nullptr, Mc, Vc, Cc, 0);
}